// round 3
// baseline (speedup 1.0000x reference)
#include <cuda_runtime.h>
#include <stdint.h>

#define N_NODES 50000
#define E_EDGES 800000
#define INC 128
#define HID 256
#define OUTC 51

// Scratch (static device globals -- allocation-free per harness rules)
__device__ float g_agg1[N_NODES * INC];
__device__ float g_x1[N_NODES * HID];
__device__ float g_agg2[N_NODES * HID];
__device__ float g_x2[N_NODES * HID];
__device__ int   g_idx_is64;

// ---------------------------------------------------------------------------
// Detect edge_index dtype: int64 (reference says so) vs int32 (JAX x64-off
// default). Reading int32 data as int64 packs two indices -> value >= 2^32
// unless the high word is 0 (prob 1/50000 per entry). 256 entries => certain.
// ---------------------------------------------------------------------------
__global__ void detect_idx(const void* __restrict__ ei) {
    if (threadIdx.x == 0) {
        const long long* p = (const long long*)ei;
        int ok = 1;
        for (int i = 0; i < 256; ++i) {
            long long v = p[i];
            if (v < 0 || v >= N_NODES) { ok = 0; break; }
        }
        g_idx_is64 = ok;
    }
}

__device__ __forceinline__ void load_edge(const void* ei, int e, int& src, int& dst) {
    if (g_idx_is64) {
        src = (int)((const long long*)ei)[e];
        dst = (int)((const long long*)ei)[E_EDGES + e];
    } else {
        src = ((const int*)ei)[e];
        dst = ((const int*)ei)[E_EDGES + e];
    }
}

// ---------------------------------------------------------------------------
// Zero the aggregation buffers (they persist across graph replays)
// ---------------------------------------------------------------------------
__global__ void zero_aggs() {
    int i = blockIdx.x * blockDim.x + threadIdx.x;
    float4 z = make_float4(0.f, 0.f, 0.f, 0.f);
    const int n1 = N_NODES * INC / 4;   // 1.6M
    const int n2 = N_NODES * HID / 4;   // 3.2M
    if (i < n1) ((float4*)g_agg1)[i] = z;
    if (i < n2) ((float4*)g_agg2)[i] = z;
}

// ---------------------------------------------------------------------------
// Scatter layer 1: agg1[dst] += w_e * x0[src]   (128 features: 1 float4/lane)
// One warp per edge.
// ---------------------------------------------------------------------------
__global__ void scatter1(const float* __restrict__ x,
                         const void* __restrict__ ei,
                         const float* __restrict__ ew) {
    int e = blockIdx.x * 8 + (threadIdx.x >> 5);
    if (e >= E_EDGES) return;
    int lane = threadIdx.x & 31;
    int src, dst;
    load_edge(ei, e, src, dst);
    float w = ew[e];
    float4 v = ((const float4*)(x + (size_t)src * INC))[lane];
    v.x *= w; v.y *= w; v.z *= w; v.w *= w;
    float* p = g_agg1 + (size_t)dst * INC + lane * 4;
    asm volatile("red.global.add.v4.f32 [%0], {%1,%2,%3,%4};"
                 :: "l"(p), "f"(v.x), "f"(v.y), "f"(v.z), "f"(v.w) : "memory");
}

// ---------------------------------------------------------------------------
// Scatter layer 2: agg2[dst] += w_e * x1[src]   (256 features: 2 float4/lane)
// ---------------------------------------------------------------------------
__global__ void scatter2(const float* __restrict__ x,
                         const void* __restrict__ ei,
                         const float* __restrict__ ew) {
    int e = blockIdx.x * 8 + (threadIdx.x >> 5);
    if (e >= E_EDGES) return;
    int lane = threadIdx.x & 31;
    int src, dst;
    load_edge(ei, e, src, dst);
    float w = ew[e];
    const float4* xr = (const float4*)(x + (size_t)src * HID);
    float* ar = g_agg2 + (size_t)dst * HID;
#pragma unroll
    for (int c = 0; c < 2; ++c) {
        int q = lane + 32 * c;
        float4 v = xr[q];
        v.x *= w; v.y *= w; v.z *= w; v.w *= w;
        float* p = ar + q * 4;
        asm volatile("red.global.add.v4.f32 [%0], {%1,%2,%3,%4};"
                     :: "l"(p), "f"(v.x), "f"(v.y), "f"(v.z), "f"(v.w) : "memory");
    }
}

// ---------------------------------------------------------------------------
// Dual-source SGEMM: C = act(A1 @ W1 + A2 @ W2 + bias)
//   A1: [N, K1], W1: [K1, M], A2: [N, K2], W2: [K2, M] (row-major, lead dim M)
// BM=128, BK=16, 256 threads, each thread computes 8 x TN.
// ---------------------------------------------------------------------------
template <int BN, int TN>
__global__ __launch_bounds__(256)
void gemm_dual(const float* __restrict__ A1, const float* __restrict__ W1, int K1,
               const float* __restrict__ A2, const float* __restrict__ W2, int K2,
               const float* __restrict__ bias, float* __restrict__ C,
               int M, int doRelu) {
    const int BM = 128, BK = 16;
    __shared__ float As[BK][BM + 1];
    __shared__ float Ws[BK][BN];

    int tid = threadIdx.x;
    int tx = tid % (BN / TN);   // column groups
    int ty = tid / (BN / TN);   // row groups (TM = 8)
    int row0 = blockIdx.x * BM;
    int col0 = blockIdx.y * BN;

    float acc[8][TN];
#pragma unroll
    for (int i = 0; i < 8; ++i)
#pragma unroll
        for (int j = 0; j < TN; ++j) acc[i][j] = 0.f;

#pragma unroll 1
    for (int s = 0; s < 2; ++s) {
        const float* A = s ? A2 : A1;
        const float* W = s ? W2 : W1;
        int K = s ? K2 : K1;
#pragma unroll 1
        for (int k0 = 0; k0 < K; k0 += BK) {
            // A tile: 128x16 as float4, transposed into As[k][row]
#pragma unroll
            for (int j = 0; j < 2; ++j) {
                int i = tid + 256 * j;   // 0..511 float4 slots
                int r = i >> 2;          // 0..127
                int kq = i & 3;          // quad within the 16 k's
                int grow = row0 + r;
                float4 v = make_float4(0.f, 0.f, 0.f, 0.f);
                if (grow < N_NODES)
                    v = *(const float4*)(A + (size_t)grow * K + k0 + kq * 4);
                As[kq * 4 + 0][r] = v.x;
                As[kq * 4 + 1][r] = v.y;
                As[kq * 4 + 2][r] = v.z;
                As[kq * 4 + 3][r] = v.w;
            }
            // W tile: 16 x BN, coalesced scalar loads, col-predicated
#pragma unroll
            for (int j = 0; j < (BK * BN) / 256; ++j) {
                int i = tid + 256 * j;
                int r = i / BN;
                int c = i % BN;
                float v = 0.f;
                if (col0 + c < M) v = W[(size_t)(k0 + r) * M + col0 + c];
                Ws[r][c] = v;
            }
            __syncthreads();
#pragma unroll
            for (int k = 0; k < BK; ++k) {
                float a[8], b[TN];
#pragma unroll
                for (int i = 0; i < 8; ++i) a[i] = As[k][ty * 8 + i];
#pragma unroll
                for (int j = 0; j < TN; ++j) b[j] = Ws[k][tx * TN + j];
#pragma unroll
                for (int i = 0; i < 8; ++i)
#pragma unroll
                    for (int j = 0; j < TN; ++j)
                        acc[i][j] = fmaf(a[i], b[j], acc[i][j]);
            }
            __syncthreads();
        }
    }

    // Epilogue
#pragma unroll
    for (int i = 0; i < 8; ++i) {
        int grow = row0 + ty * 8 + i;
        if (grow >= N_NODES) continue;
        float* crow = C + (size_t)grow * M;
#pragma unroll
        for (int j = 0; j < TN; ++j) {
            int gcol = col0 + tx * TN + j;
            if (gcol >= M) continue;
            float v = acc[i][j] + bias[gcol];
            if (doRelu) v = fmaxf(v, 0.f);
            crow[gcol] = v;
        }
    }
}

// ---------------------------------------------------------------------------
extern "C" void kernel_launch(void* const* d_in, const int* in_sizes, int n_in,
                              void* d_out, int out_size) {
    const float* x0      = (const float*)d_in[0];
    const void*  ei      = d_in[1];             // int32 or int64, detected on device
    const float* ew      = (const float*)d_in[2];
    const float* w_rel1  = (const float*)d_in[3];
    const float* b1      = (const float*)d_in[4];
    const float* w_root1 = (const float*)d_in[5];
    const float* w_rel2  = (const float*)d_in[6];
    const float* b2      = (const float*)d_in[7];
    const float* w_root2 = (const float*)d_in[8];
    const float* lin_w   = (const float*)d_in[9];
    const float* lin_b   = (const float*)d_in[10];
    float*       out     = (float*)d_out;

    float *agg1, *x1, *agg2, *x2;
    cudaGetSymbolAddress((void**)&agg1, g_agg1);
    cudaGetSymbolAddress((void**)&x1,   g_x1);
    cudaGetSymbolAddress((void**)&agg2, g_agg2);
    cudaGetSymbolAddress((void**)&x2,   g_x2);

    const int nblk = (N_NODES + 127) / 128;   // 391

    // 0) detect index dtype
    detect_idx<<<1, 32>>>(ei);
    // 1) zero agg buffers
    {
        int n = N_NODES * HID / 4;
        zero_aggs<<<(n + 255) / 256, 256>>>();
    }
    // 2) scatter layer 1
    scatter1<<<(E_EDGES + 7) / 8, 256>>>(x0, ei, ew);
    // 3) x1 = relu(agg1 @ w_rel1 + x0 @ w_root1 + b1)
    gemm_dual<128, 8><<<dim3(nblk, 2), 256>>>(agg1, w_rel1, INC,
                                              x0, w_root1, INC,
                                              b1, x1, HID, 1);
    // 4) scatter layer 2
    scatter2<<<(E_EDGES + 7) / 8, 256>>>(x1, ei, ew);
    // 5) x2 = relu(agg2 @ w_rel2 + x1 @ w_root2 + b2)
    gemm_dual<128, 8><<<dim3(nblk, 2), 256>>>(agg2, w_rel2, HID,
                                              x1, w_root2, HID,
                                              b2, x2, HID, 1);
    // 6) out = x1 @ lin_w[0:256] + x2 @ lin_w[256:512] + lin_b
    gemm_dual<64, 4><<<dim3(nblk, 1), 256>>>(x1, lin_w, HID,
                                             x2, lin_w + (size_t)HID * OUTC, HID,
                                             lin_b, out, OUTC, 0);
}

// round 4
// speedup vs baseline: 1.3878x; 1.3878x over previous
#include <cuda_runtime.h>
#include <stdint.h>

#define N_NODES 50000
#define E_EDGES 800000
#define INC 128
#define HID 256
#define OUTC 51

// Scratch (static device globals -- allocation-free per harness rules)
__device__ float g_agg1[N_NODES * INC];
__device__ float g_x1[N_NODES * HID];
__device__ float g_agg2[N_NODES * HID];
__device__ float g_x2[N_NODES * HID];
__device__ int   g_idx_is64;

// CSR build scratch (rebuilt every call -- no caching across calls)
__device__ int   g_deg[N_NODES];
__device__ int   g_off[N_NODES + 1];
__device__ int   g_cur[N_NODES];
__device__ int   g_esrc[E_EDGES];
__device__ float g_eww[E_EDGES];

// ---------------------------------------------------------------------------
// Detect edge_index dtype: int64 vs int32 (JAX x64-off default). Reading
// int32 data as int64 packs two indices -> value outside [0,N) almost surely.
// Parallel: 32 threads x 8 entries + ballot.
// ---------------------------------------------------------------------------
__global__ void detect_idx(const void* __restrict__ ei) {
    int t = threadIdx.x;
    const long long* p = (const long long*)ei;
    int bad = 0;
    for (int i = t; i < 256; i += 32) {
        long long v = p[i];
        if (v < 0 || v >= N_NODES) bad = 1;
    }
    unsigned m = __ballot_sync(0xffffffffu, bad);
    if (t == 0) g_idx_is64 = (m == 0u);
}

__device__ __forceinline__ void load_edge(const void* ei, int e, int& src, int& dst) {
    if (g_idx_is64) {
        src = (int)((const long long*)ei)[e];
        dst = (int)((const long long*)ei)[E_EDGES + e];
    } else {
        src = ((const int*)ei)[e];
        dst = ((const int*)ei)[E_EDGES + e];
    }
}

// ---------------------------------------------------------------------------
// CSR construction: histogram -> scan -> bucket
// ---------------------------------------------------------------------------
__global__ void zero_deg() {
    int i = blockIdx.x * blockDim.x + threadIdx.x;
    if (i < N_NODES) g_deg[i] = 0;
}

__global__ void hist_dst(const void* __restrict__ ei) {
    int e = blockIdx.x * blockDim.x + threadIdx.x;
    if (e >= E_EDGES) return;
    int src, dst;
    load_edge(ei, e, src, dst);
    atomicAdd(&g_deg[dst], 1);
}

__global__ __launch_bounds__(1024)
void scan_deg() {
    __shared__ int part[1024];
    int t = threadIdx.x;
    const int CH = (N_NODES + 1023) / 1024;   // 49
    int beg = t * CH;
    int end = beg + CH; if (end > N_NODES) end = N_NODES;
    int s = 0;
    for (int i = beg; i < end && i >= 0; ++i) s += g_deg[i];
    part[t] = s;
    __syncthreads();
    // Hillis-Steele inclusive scan
    for (int off = 1; off < 1024; off <<= 1) {
        int v = (t >= off) ? part[t - off] : 0;
        __syncthreads();
        part[t] += v;
        __syncthreads();
    }
    int run = (t == 0) ? 0 : part[t - 1];  // exclusive prefix
    for (int i = beg; i < end && i >= 0; ++i) {
        g_off[i] = run;
        g_cur[i] = run;
        run += g_deg[i];
    }
    if (t == 1023) g_off[N_NODES] = part[1023];
}

__global__ void bucket_edges(const void* __restrict__ ei,
                             const float* __restrict__ ew) {
    int e = blockIdx.x * blockDim.x + threadIdx.x;
    if (e >= E_EDGES) return;
    int src, dst;
    load_edge(ei, e, src, dst);
    int pos = atomicAdd(&g_cur[dst], 1);
    g_esrc[pos] = src;
    g_eww[pos]  = ew[e];
}

// ---------------------------------------------------------------------------
// CSR aggregation: one warp per dst node, register accumulation, single store.
// No atomics, halves L2 write traffic vs RED.
// ---------------------------------------------------------------------------
__global__ __launch_bounds__(256)
void agg_csr_128(const float* __restrict__ x, float* __restrict__ out) {
    int d = blockIdx.x * 8 + (threadIdx.x >> 5);
    if (d >= N_NODES) return;
    int lane = threadIdx.x & 31;
    int beg = g_off[d], end = g_off[d + 1];
    float4 acc = make_float4(0.f, 0.f, 0.f, 0.f);
    int k = beg;
    for (; k + 1 < end; k += 2) {
        int   s0 = g_esrc[k],     s1 = g_esrc[k + 1];
        float w0 = g_eww[k],      w1 = g_eww[k + 1];
        float4 v0 = ((const float4*)(x + (size_t)s0 * INC))[lane];
        float4 v1 = ((const float4*)(x + (size_t)s1 * INC))[lane];
        acc.x = fmaf(w0, v0.x, acc.x); acc.y = fmaf(w0, v0.y, acc.y);
        acc.z = fmaf(w0, v0.z, acc.z); acc.w = fmaf(w0, v0.w, acc.w);
        acc.x = fmaf(w1, v1.x, acc.x); acc.y = fmaf(w1, v1.y, acc.y);
        acc.z = fmaf(w1, v1.z, acc.z); acc.w = fmaf(w1, v1.w, acc.w);
    }
    if (k < end) {
        int s = g_esrc[k]; float w = g_eww[k];
        float4 v = ((const float4*)(x + (size_t)s * INC))[lane];
        acc.x = fmaf(w, v.x, acc.x); acc.y = fmaf(w, v.y, acc.y);
        acc.z = fmaf(w, v.z, acc.z); acc.w = fmaf(w, v.w, acc.w);
    }
    ((float4*)(out + (size_t)d * INC))[lane] = acc;
}

__global__ __launch_bounds__(256)
void agg_csr_256(const float* __restrict__ x, float* __restrict__ out) {
    int d = blockIdx.x * 8 + (threadIdx.x >> 5);
    if (d >= N_NODES) return;
    int lane = threadIdx.x & 31;
    int beg = g_off[d], end = g_off[d + 1];
    float4 a0 = make_float4(0.f, 0.f, 0.f, 0.f);
    float4 a1 = make_float4(0.f, 0.f, 0.f, 0.f);
    for (int k = beg; k < end; ++k) {
        int s = g_esrc[k]; float w = g_eww[k];
        const float4* xr = (const float4*)(x + (size_t)s * HID);
        float4 v0 = xr[lane];
        float4 v1 = xr[lane + 32];
        a0.x = fmaf(w, v0.x, a0.x); a0.y = fmaf(w, v0.y, a0.y);
        a0.z = fmaf(w, v0.z, a0.z); a0.w = fmaf(w, v0.w, a0.w);
        a1.x = fmaf(w, v1.x, a1.x); a1.y = fmaf(w, v1.y, a1.y);
        a1.z = fmaf(w, v1.z, a1.z); a1.w = fmaf(w, v1.w, a1.w);
    }
    float4* orow = (float4*)(out + (size_t)d * HID);
    orow[lane]      = a0;
    orow[lane + 32] = a1;
}

// ---------------------------------------------------------------------------
// Dual-source SGEMM: C = act(A1 @ W1 + A2 @ W2 + bias)
// BM=128, BK=16, 256 threads, each thread computes 8 x TN.
// ---------------------------------------------------------------------------
template <int BN, int TN>
__global__ __launch_bounds__(256)
void gemm_dual(const float* __restrict__ A1, const float* __restrict__ W1, int K1,
               const float* __restrict__ A2, const float* __restrict__ W2, int K2,
               const float* __restrict__ bias, float* __restrict__ C,
               int M, int doRelu) {
    const int BM = 128, BK = 16;
    __shared__ float As[BK][BM + 1];
    __shared__ float Ws[BK][BN];

    int tid = threadIdx.x;
    int tx = tid % (BN / TN);   // column groups
    int ty = tid / (BN / TN);   // row groups (TM = 8)
    int row0 = blockIdx.x * BM;
    int col0 = blockIdx.y * BN;

    float acc[8][TN];
#pragma unroll
    for (int i = 0; i < 8; ++i)
#pragma unroll
        for (int j = 0; j < TN; ++j) acc[i][j] = 0.f;

#pragma unroll 1
    for (int s = 0; s < 2; ++s) {
        const float* A = s ? A2 : A1;
        const float* W = s ? W2 : W1;
        int K = s ? K2 : K1;
#pragma unroll 1
        for (int k0 = 0; k0 < K; k0 += BK) {
            // A tile: 128x16 as float4, transposed into As[k][row]
#pragma unroll
            for (int j = 0; j < 2; ++j) {
                int i = tid + 256 * j;   // 0..511 float4 slots
                int r = i >> 2;          // 0..127
                int kq = i & 3;          // quad within the 16 k's
                int grow = row0 + r;
                float4 v = make_float4(0.f, 0.f, 0.f, 0.f);
                if (grow < N_NODES)
                    v = *(const float4*)(A + (size_t)grow * K + k0 + kq * 4);
                As[kq * 4 + 0][r] = v.x;
                As[kq * 4 + 1][r] = v.y;
                As[kq * 4 + 2][r] = v.z;
                As[kq * 4 + 3][r] = v.w;
            }
            // W tile: 16 x BN, coalesced scalar loads, col-predicated
#pragma unroll
            for (int j = 0; j < (BK * BN) / 256; ++j) {
                int i = tid + 256 * j;
                int r = i / BN;
                int c = i % BN;
                float v = 0.f;
                if (col0 + c < M) v = W[(size_t)(k0 + r) * M + col0 + c];
                Ws[r][c] = v;
            }
            __syncthreads();
#pragma unroll
            for (int k = 0; k < BK; ++k) {
                float a[8], b[TN];
#pragma unroll
                for (int i = 0; i < 8; ++i) a[i] = As[k][ty * 8 + i];
#pragma unroll
                for (int j = 0; j < TN; ++j) b[j] = Ws[k][tx * TN + j];
#pragma unroll
                for (int i = 0; i < 8; ++i)
#pragma unroll
                    for (int j = 0; j < TN; ++j)
                        acc[i][j] = fmaf(a[i], b[j], acc[i][j]);
            }
            __syncthreads();
        }
    }

    // Epilogue
#pragma unroll
    for (int i = 0; i < 8; ++i) {
        int grow = row0 + ty * 8 + i;
        if (grow >= N_NODES) continue;
        float* crow = C + (size_t)grow * M;
#pragma unroll
        for (int j = 0; j < TN; ++j) {
            int gcol = col0 + tx * TN + j;
            if (gcol >= M) continue;
            float v = acc[i][j] + bias[gcol];
            if (doRelu) v = fmaxf(v, 0.f);
            crow[gcol] = v;
        }
    }
}

// ---------------------------------------------------------------------------
extern "C" void kernel_launch(void* const* d_in, const int* in_sizes, int n_in,
                              void* d_out, int out_size) {
    const float* x0      = (const float*)d_in[0];
    const void*  ei      = d_in[1];             // int32 or int64, detected on device
    const float* ew      = (const float*)d_in[2];
    const float* w_rel1  = (const float*)d_in[3];
    const float* b1      = (const float*)d_in[4];
    const float* w_root1 = (const float*)d_in[5];
    const float* w_rel2  = (const float*)d_in[6];
    const float* b2      = (const float*)d_in[7];
    const float* w_root2 = (const float*)d_in[8];
    const float* lin_w   = (const float*)d_in[9];
    const float* lin_b   = (const float*)d_in[10];
    float*       out     = (float*)d_out;

    float *agg1, *x1, *agg2, *x2;
    cudaGetSymbolAddress((void**)&agg1, g_agg1);
    cudaGetSymbolAddress((void**)&x1,   g_x1);
    cudaGetSymbolAddress((void**)&agg2, g_agg2);
    cudaGetSymbolAddress((void**)&x2,   g_x2);

    const int nblk  = (N_NODES + 127) / 128;   // 391
    const int eblk  = (E_EDGES + 255) / 256;   // 3125
    const int wblk  = (N_NODES + 7) / 8;       // 6250 (warp per dst, 8 warps/CTA)

    // 0) detect index dtype
    detect_idx<<<1, 32>>>(ei);
    // 1) build CSR (reused by both layers; graph is static within a call)
    zero_deg<<<(N_NODES + 255) / 256, 256>>>();
    hist_dst<<<eblk, 256>>>(ei);
    scan_deg<<<1, 1024>>>();
    bucket_edges<<<eblk, 256>>>(ei, ew);
    // 2) agg1 = segment_sum(w_e * x0[src])
    agg_csr_128<<<wblk, 256>>>(x0, agg1);
    // 3) x1 = relu(agg1 @ w_rel1 + x0 @ w_root1 + b1)
    gemm_dual<64, 4><<<dim3(nblk, 4), 256>>>(agg1, w_rel1, INC,
                                             x0, w_root1, INC,
                                             b1, x1, HID, 1);
    // 4) agg2 = segment_sum(w_e * x1[src])
    agg_csr_256<<<wblk, 256>>>(x1, agg2);
    // 5) x2 = relu(agg2 @ w_rel2 + x1 @ w_root2 + b2)
    gemm_dual<64, 4><<<dim3(nblk, 4), 256>>>(agg2, w_rel2, HID,
                                             x1, w_root2, HID,
                                             b2, x2, HID, 1);
    // 6) out = x1 @ lin_w[0:256] + x2 @ lin_w[256:512] + lin_b
    gemm_dual<64, 4><<<dim3(nblk, 1), 256>>>(x1, lin_w, HID,
                                             x2, lin_w + (size_t)HID * OUTC, HID,
                                             lin_b, out, OUTC, 0);
}

// round 6
// speedup vs baseline: 2.2312x; 1.6077x over previous
#include <cuda_runtime.h>
#include <cuda_bf16.h>
#include <stdint.h>

#define N_NODES 50000
#define E_EDGES 800000
#define INC 128
#define HID 256
#define OUTC 51
#define NB_SCAN 196   // ceil(50000/256)

// ---------------------------------------------------------------------------
// Scratch (static device globals -- allocation-free per harness rules)
// ---------------------------------------------------------------------------
__device__ __align__(16) __nv_bfloat16 g_x0h[N_NODES * INC], g_x0l[N_NODES * INC];
__device__ __align__(16) __nv_bfloat16 g_a1h[N_NODES * INC], g_a1l[N_NODES * INC];
__device__ __align__(16) float         g_x1f[N_NODES * HID];
__device__ __align__(16) __nv_bfloat16 g_x1h[N_NODES * HID], g_x1l[N_NODES * HID];
__device__ __align__(16) __nv_bfloat16 g_a2h[N_NODES * HID], g_a2l[N_NODES * HID];
__device__ __align__(16) __nv_bfloat16 g_x2h[N_NODES * HID], g_x2l[N_NODES * HID];
// transposed+split weights: Wt[n][k] = W[k][n]
__device__ __align__(16) __nv_bfloat16 g_wr1h[HID * INC],  g_wr1l[HID * INC];
__device__ __align__(16) __nv_bfloat16 g_wo1h[HID * INC],  g_wo1l[HID * INC];
__device__ __align__(16) __nv_bfloat16 g_wr2h[HID * HID],  g_wr2l[HID * HID];
__device__ __align__(16) __nv_bfloat16 g_wo2h[HID * HID],  g_wo2l[HID * HID];
__device__ __align__(16) __nv_bfloat16 g_linh[OUTC * 2 * HID], g_linl[OUTC * 2 * HID];
// CSR
__device__ int   g_deg[N_NODES];
__device__ int   g_off[N_NODES + 1];
__device__ int   g_cur[N_NODES];
__device__ int   g_esrc[E_EDGES];
__device__ float g_eww[E_EDGES];
__device__ int   g_bsum[256];
__device__ int   g_bpre[256];
__device__ int   g_idx_is64;

// ---------------------------------------------------------------------------
// PTX helpers (baseline PTX only -- no sm_103a-accelerated features)
// ---------------------------------------------------------------------------
__device__ __forceinline__ uint32_t smem_u32(const void* p) {
    uint32_t a;
    asm("{ .reg .u64 t; cvta.to.shared.u64 t, %1; cvt.u32.u64 %0, t; }" : "=r"(a) : "l"(p));
    return a;
}
__device__ __forceinline__ void ldsm4(uint32_t addr, uint32_t& r0, uint32_t& r1,
                                      uint32_t& r2, uint32_t& r3) {
    asm volatile("ldmatrix.sync.aligned.m8n8.x4.shared.b16 {%0,%1,%2,%3}, [%4];"
                 : "=r"(r0), "=r"(r1), "=r"(r2), "=r"(r3) : "r"(addr));
}
__device__ __forceinline__ void mma16816(float* c, const uint32_t* a, const uint32_t* b) {
    asm volatile("mma.sync.aligned.m16n8k16.row.col.f32.bf16.bf16.f32 "
                 "{%0,%1,%2,%3}, {%4,%5,%6,%7}, {%8,%9}, {%0,%1,%2,%3};"
                 : "+f"(c[0]), "+f"(c[1]), "+f"(c[2]), "+f"(c[3])
                 : "r"(a[0]), "r"(a[1]), "r"(a[2]), "r"(a[3]), "r"(b[0]), "r"(b[1]));
}
// swizzled smem unit address inside a [128 rows x 32 bf16] tile (16B units, 4/row)
__device__ __forceinline__ uint32_t tile_addr(uint32_t base, int r, int u) {
    int up = u ^ ((r >> 1) & 3);
    return base + (uint32_t)(r * 4 + up) * 16u;
}

// ---------------------------------------------------------------------------
// dtype detect (int64 per reference vs int32 from JAX x64-off)
// ---------------------------------------------------------------------------
__global__ void detect_idx(const void* __restrict__ ei) {
    int t = threadIdx.x;
    const long long* p = (const long long*)ei;
    int bad = 0;
    for (int i = t; i < 256; i += 32) {
        long long v = p[i];
        if (v < 0 || v >= N_NODES) bad = 1;
    }
    unsigned m = __ballot_sync(0xffffffffu, bad);
    if (t == 0) g_idx_is64 = (m == 0u);
}
__device__ __forceinline__ void load_edge(const void* ei, int e, int& src, int& dst) {
    if (g_idx_is64) {
        src = (int)((const long long*)ei)[e];
        dst = (int)((const long long*)ei)[E_EDGES + e];
    } else {
        src = ((const int*)ei)[e];
        dst = ((const int*)ei)[E_EDGES + e];
    }
}

// ---------------------------------------------------------------------------
// CSR build: histogram -> 3-kernel scan -> bucket
// ---------------------------------------------------------------------------
__global__ void zero_deg() {
    int i = blockIdx.x * blockDim.x + threadIdx.x;
    if (i < N_NODES) g_deg[i] = 0;
}
__global__ void hist_dst(const void* __restrict__ ei) {
    int e = blockIdx.x * blockDim.x + threadIdx.x;
    if (e >= E_EDGES) return;
    int src, dst;
    load_edge(ei, e, src, dst);
    atomicAdd(&g_deg[dst], 1);
}
__global__ void block_sum() {
    __shared__ int s[256];
    int b = blockIdx.x, t = threadIdx.x, i = b * 256 + t;
    s[t] = (i < N_NODES) ? g_deg[i] : 0;
    __syncthreads();
    for (int o = 128; o > 0; o >>= 1) { if (t < o) s[t] += s[t + o]; __syncthreads(); }
    if (t == 0) g_bsum[b] = s[0];
}
__global__ void scan_bsum() {
    __shared__ int s[256];
    int t = threadIdx.x;
    s[t] = (t < NB_SCAN) ? g_bsum[t] : 0;
    __syncthreads();
    for (int o = 1; o < 256; o <<= 1) {
        int v = (t >= o) ? s[t - o] : 0;
        __syncthreads();
        s[t] += v;
        __syncthreads();
    }
    g_bpre[t] = s[t];
}
__global__ void write_off() {
    __shared__ int s[256];
    int b = blockIdx.x, t = threadIdx.x, i = b * 256 + t;
    int v = (i < N_NODES) ? g_deg[i] : 0;
    s[t] = v;
    __syncthreads();
    for (int o = 1; o < 256; o <<= 1) {
        int u = (t >= o) ? s[t - o] : 0;
        __syncthreads();
        s[t] += u;
        __syncthreads();
    }
    int base = (b == 0) ? 0 : g_bpre[b - 1];
    int off = base + s[t] - v;
    if (i < N_NODES) {
        g_off[i] = off;
        g_cur[i] = off;
        if (i == N_NODES - 1) g_off[N_NODES] = off + v;
    }
}
__global__ void bucket_edges(const void* __restrict__ ei, const float* __restrict__ ew) {
    int e = blockIdx.x * blockDim.x + threadIdx.x;
    if (e >= E_EDGES) return;
    int src, dst;
    load_edge(ei, e, src, dst);
    int pos = atomicAdd(&g_cur[dst], 1);
    g_esrc[pos] = src;
    g_eww[pos]  = ew[e];
}

// ---------------------------------------------------------------------------
// bf16 hi/lo split helpers
// ---------------------------------------------------------------------------
__device__ __forceinline__ void split1(float v, __nv_bfloat16& h, __nv_bfloat16& l) {
    h = __float2bfloat16(v);
    l = __float2bfloat16(v - __bfloat162float(h));
}
__device__ __forceinline__ void store_split4(float4 a, __nv_bfloat16* ph, __nv_bfloat16* pl) {
    __nv_bfloat16 h0, h1, h2, h3, l0, l1, l2, l3;
    split1(a.x, h0, l0); split1(a.y, h1, l1); split1(a.z, h2, l2); split1(a.w, h3, l3);
    ((__nv_bfloat162*)ph)[0] = __halves2bfloat162(h0, h1);
    ((__nv_bfloat162*)ph)[1] = __halves2bfloat162(h2, h3);
    ((__nv_bfloat162*)pl)[0] = __halves2bfloat162(l0, l1);
    ((__nv_bfloat162*)pl)[1] = __halves2bfloat162(l2, l3);
}

__global__ void cvt_split(const float* __restrict__ src,
                          __nv_bfloat16* __restrict__ h,
                          __nv_bfloat16* __restrict__ l, int n) {
    int i = blockIdx.x * blockDim.x + threadIdx.x;
    if (i >= n) return;
    __nv_bfloat16 hh, ll;
    split1(src[i], hh, ll);
    h[i] = hh; l[i] = ll;
}

// W[K][M] fp32 -> Wt[M][K] split bf16
__global__ void transpose_split(const float* __restrict__ W, int K, int M,
                                __nv_bfloat16* __restrict__ th,
                                __nv_bfloat16* __restrict__ tl) {
    int i = blockIdx.x * blockDim.x + threadIdx.x;
    if (i >= K * M) return;
    int k = i / M, m = i % M;
    __nv_bfloat16 hh, ll;
    split1(W[i], hh, ll);
    th[(size_t)m * K + k] = hh;
    tl[(size_t)m * K + k] = ll;
}

// ---------------------------------------------------------------------------
// CSR aggregation (warp per dst, fp32 register accumulate, bf16-split output)
// ---------------------------------------------------------------------------
__global__ __launch_bounds__(256)
void agg_csr_128(const float* __restrict__ x,
                 __nv_bfloat16* __restrict__ oh, __nv_bfloat16* __restrict__ ol) {
    int d = blockIdx.x * 8 + (threadIdx.x >> 5);
    if (d >= N_NODES) return;
    int lane = threadIdx.x & 31;
    int beg = g_off[d], end = g_off[d + 1];
    float4 acc = make_float4(0.f, 0.f, 0.f, 0.f);
    for (int k = beg; k < end; ++k) {
        int s = g_esrc[k]; float w = g_eww[k];
        float4 v = ((const float4*)(x + (size_t)s * INC))[lane];
        acc.x = fmaf(w, v.x, acc.x); acc.y = fmaf(w, v.y, acc.y);
        acc.z = fmaf(w, v.z, acc.z); acc.w = fmaf(w, v.w, acc.w);
    }
    store_split4(acc, oh + (size_t)d * INC + lane * 4, ol + (size_t)d * INC + lane * 4);
}

__global__ __launch_bounds__(256)
void agg_csr_256(const float* __restrict__ x,
                 __nv_bfloat16* __restrict__ oh, __nv_bfloat16* __restrict__ ol) {
    int d = blockIdx.x * 8 + (threadIdx.x >> 5);
    if (d >= N_NODES) return;
    int lane = threadIdx.x & 31;
    int beg = g_off[d], end = g_off[d + 1];
    float4 a0 = make_float4(0.f, 0.f, 0.f, 0.f);
    float4 a1 = make_float4(0.f, 0.f, 0.f, 0.f);
    for (int k = beg; k < end; ++k) {
        int s = g_esrc[k]; float w = g_eww[k];
        const float4* xr = (const float4*)(x + (size_t)s * HID);
        float4 v0 = xr[lane];
        float4 v1 = xr[lane + 32];
        a0.x = fmaf(w, v0.x, a0.x); a0.y = fmaf(w, v0.y, a0.y);
        a0.z = fmaf(w, v0.z, a0.z); a0.w = fmaf(w, v0.w, a0.w);
        a1.x = fmaf(w, v1.x, a1.x); a1.y = fmaf(w, v1.y, a1.y);
        a1.z = fmaf(w, v1.z, a1.z); a1.w = fmaf(w, v1.w, a1.w);
    }
    store_split4(a0, oh + (size_t)d * HID + lane * 4,       ol + (size_t)d * HID + lane * 4);
    store_split4(a1, oh + (size_t)d * HID + 128 + lane * 4, ol + (size_t)d * HID + 128 + lane * 4);
}

// ---------------------------------------------------------------------------
// bf16 split-precision dual-source GEMM via mma.sync (portable tensor core)
//   C[128 x 128-tile] = sum_s A_s[128,Ks] @ B_s^T   with 3 split terms
//   A row-major [N,K]; B pre-transposed Bt[M][K] (k contiguous = col-major B)
//   8 warps: 4(m) x 2(n), warp tile 32x64, mma m16n8k16.
// ---------------------------------------------------------------------------
__device__ __forceinline__ void stage(__nv_bfloat16* dst, const __nv_bfloat16* src,
                                      int pitch, int kcol, int rows_valid, int tid) {
#pragma unroll
    for (int h = 0; h < 2; ++h) {
        int U = tid + h * 256;        // 512 16B-units per tile
        int r = U >> 2, u = U & 3;
        int up = u ^ ((r >> 1) & 3);
        uint4 v = make_uint4(0, 0, 0, 0);
        if (r < rows_valid)
            v = *(const uint4*)(src + (size_t)r * pitch + kcol + u * 8);
        *(uint4*)(dst + r * 32 + up * 8) = v;
    }
}

__global__ __launch_bounds__(256)
void gemm_mma(const __nv_bfloat16* __restrict__ A1h, const __nv_bfloat16* __restrict__ A1l, int K1,
              const __nv_bfloat16* __restrict__ A2h, const __nv_bfloat16* __restrict__ A2l, int K2,
              const __nv_bfloat16* __restrict__ B1h, const __nv_bfloat16* __restrict__ B1l, int pb1,
              const __nv_bfloat16* __restrict__ B2h, const __nv_bfloat16* __restrict__ B2l, int pb2,
              const float* __restrict__ bias,
              float* __restrict__ outF, __nv_bfloat16* __restrict__ outH,
              __nv_bfloat16* __restrict__ outL, int Mout, int doRelu) {
    __shared__ __align__(16) __nv_bfloat16 sAh[128 * 32], sAl[128 * 32];
    __shared__ __align__(16) __nv_bfloat16 sBh[128 * 32], sBl[128 * 32];

    int tid = threadIdx.x, wid = tid >> 5, lane = tid & 31;
    int wm = (wid & 3) * 32;      // warp row offset in 128
    int wn = (wid >> 2) * 64;     // warp col offset in 128
    int row0 = blockIdx.x * 128;
    int col0 = blockIdx.y * 128;
    int rowsA = N_NODES - row0; if (rowsA > 128) rowsA = 128;
    int rowsB = Mout - col0;    if (rowsB > 128) rowsB = 128; if (rowsB < 0) rowsB = 0;

    uint32_t bAh = smem_u32(sAh), bAl = smem_u32(sAl);
    uint32_t bBh = smem_u32(sBh), bBl = smem_u32(sBl);

    float acc[2][8][4];
#pragma unroll
    for (int i = 0; i < 2; ++i)
#pragma unroll
        for (int j = 0; j < 8; ++j)
#pragma unroll
            for (int q = 0; q < 4; ++q) acc[i][j][q] = 0.f;

    for (int s = 0; s < 2; ++s) {
        const __nv_bfloat16* Ah = (s ? A2h : A1h);
        const __nv_bfloat16* Al = (s ? A2l : A1l);
        const __nv_bfloat16* Bh = (s ? B2h : B1h);
        const __nv_bfloat16* Bl = (s ? B2l : B1l);
        int K  = s ? K2 : K1;
        int pb = s ? pb2 : pb1;
        const __nv_bfloat16* Ah0 = Ah + (size_t)row0 * K;
        const __nv_bfloat16* Al0 = Al + (size_t)row0 * K;
        const __nv_bfloat16* Bh0 = Bh + (size_t)col0 * pb;
        const __nv_bfloat16* Bl0 = Bl + (size_t)col0 * pb;

        for (int kc = 0; kc < K; kc += 32) {
            stage(sAh, Ah0, K, kc, rowsA, tid);
            stage(sAl, Al0, K, kc, rowsA, tid);
            stage(sBh, Bh0, pb, kc, rowsB, tid);
            stage(sBl, Bl0, pb, kc, rowsB, tid);
            __syncthreads();

#pragma unroll
            for (int ks = 0; ks < 2; ++ks) {
                int ksu = ks * 2;
                // A fragments (hi & lo), 2 m-tiles of 16 rows
                uint32_t fah[2][4], fal[2][4];
#pragma unroll
                for (int mt = 0; mt < 2; ++mt) {
                    int r = wm + mt * 16 + (lane & 15);
                    int u = ksu + (lane >> 4);
                    ldsm4(tile_addr(bAh, r, u), fah[mt][0], fah[mt][1], fah[mt][2], fah[mt][3]);
                    ldsm4(tile_addr(bAl, r, u), fal[mt][0], fal[mt][1], fal[mt][2], fal[mt][3]);
                }
                // B fragments: 4 ldsm.x4, each = 2 n-groups of 8
                uint32_t fbh[4][4], fbl[4][4];
#pragma unroll
                for (int q = 0; q < 4; ++q) {
                    int r = wn + q * 16 + (lane & 7) + ((lane & 16) ? 8 : 0);
                    int u = ksu + ((lane >> 3) & 1);
                    ldsm4(tile_addr(bBh, r, u), fbh[q][0], fbh[q][1], fbh[q][2], fbh[q][3]);
                    ldsm4(tile_addr(bBl, r, u), fbl[q][0], fbl[q][1], fbl[q][2], fbl[q][3]);
                }
                // 3 split combos: hh, hl, lh
#pragma unroll
                for (int mt = 0; mt < 2; ++mt)
#pragma unroll
                    for (int ng = 0; ng < 8; ++ng) {
                        const uint32_t* bpH = &fbh[ng >> 1][(ng & 1) * 2];
                        const uint32_t* bpL = &fbl[ng >> 1][(ng & 1) * 2];
                        mma16816(acc[mt][ng], fah[mt], bpH);
                        mma16816(acc[mt][ng], fah[mt], bpL);
                        mma16816(acc[mt][ng], fal[mt], bpH);
                    }
            }
            __syncthreads();
        }
    }

    // Epilogue
#pragma unroll
    for (int mt = 0; mt < 2; ++mt) {
        int rg = row0 + wm + mt * 16 + (lane >> 2);
#pragma unroll
        for (int half = 0; half < 2; ++half) {
            int r = rg + half * 8;
            if (r >= N_NODES) continue;
#pragma unroll
            for (int ng = 0; ng < 8; ++ng) {
                int c0 = col0 + wn + ng * 8 + (lane & 3) * 2;
#pragma unroll
                for (int q = 0; q < 2; ++q) {
                    int c = c0 + q;
                    if (c >= Mout) continue;
                    float v = acc[mt][ng][half * 2 + q] + bias[c];
                    if (doRelu) v = fmaxf(v, 0.f);
                    size_t idx = (size_t)r * Mout + c;
                    if (outF) outF[idx] = v;
                    if (outH) {
                        __nv_bfloat16 hh, ll;
                        split1(v, hh, ll);
                        outH[idx] = hh;
                        outL[idx] = ll;
                    }
                }
            }
        }
    }
}

// ---------------------------------------------------------------------------
extern "C" void kernel_launch(void* const* d_in, const int* in_sizes, int n_in,
                              void* d_out, int out_size) {
    const float* x0      = (const float*)d_in[0];
    const void*  ei      = d_in[1];
    const float* ew      = (const float*)d_in[2];
    const float* w_rel1  = (const float*)d_in[3];
    const float* b1      = (const float*)d_in[4];
    const float* w_root1 = (const float*)d_in[5];
    const float* w_rel2  = (const float*)d_in[6];
    const float* b2      = (const float*)d_in[7];
    const float* w_root2 = (const float*)d_in[8];
    const float* lin_w   = (const float*)d_in[9];
    const float* lin_b   = (const float*)d_in[10];
    float*       out     = (float*)d_out;

#define SYM(p, s) cudaGetSymbolAddress((void**)&p, s)
    __nv_bfloat16 *x0h, *x0l, *a1h, *a1l, *x1h, *x1l, *a2h, *a2l, *x2h, *x2l;
    __nv_bfloat16 *wr1h, *wr1l, *wo1h, *wo1l, *wr2h, *wr2l, *wo2h, *wo2l, *linh, *linl;
    float *x1f;
    SYM(x0h, g_x0h); SYM(x0l, g_x0l); SYM(a1h, g_a1h); SYM(a1l, g_a1l);
    SYM(x1f, g_x1f); SYM(x1h, g_x1h); SYM(x1l, g_x1l);
    SYM(a2h, g_a2h); SYM(a2l, g_a2l); SYM(x2h, g_x2h); SYM(x2l, g_x2l);
    SYM(wr1h, g_wr1h); SYM(wr1l, g_wr1l); SYM(wo1h, g_wo1h); SYM(wo1l, g_wo1l);
    SYM(wr2h, g_wr2h); SYM(wr2l, g_wr2l); SYM(wo2h, g_wo2h); SYM(wo2l, g_wo2l);
    SYM(linh, g_linh); SYM(linl, g_linl);
#undef SYM

    const int eblk = (E_EDGES + 255) / 256;
    const int wblk = (N_NODES + 7) / 8;
    const int gblk = (N_NODES + 127) / 128;   // 391

    // 0) dtype detect + input conversions (independent of CSR)
    detect_idx<<<1, 32>>>(ei);
    cvt_split<<<(N_NODES * INC + 255) / 256, 256>>>(x0, x0h, x0l, N_NODES * INC);
    transpose_split<<<(INC * HID + 255) / 256, 256>>>(w_rel1, INC, HID, wr1h, wr1l);
    transpose_split<<<(INC * HID + 255) / 256, 256>>>(w_root1, INC, HID, wo1h, wo1l);
    transpose_split<<<(HID * HID + 255) / 256, 256>>>(w_rel2, HID, HID, wr2h, wr2l);
    transpose_split<<<(HID * HID + 255) / 256, 256>>>(w_root2, HID, HID, wo2h, wo2l);
    transpose_split<<<(2 * HID * OUTC + 255) / 256, 256>>>(lin_w, 2 * HID, OUTC, linh, linl);

    // 1) CSR build
    zero_deg<<<NB_SCAN, 256>>>();
    hist_dst<<<eblk, 256>>>(ei);
    block_sum<<<NB_SCAN, 256>>>();
    scan_bsum<<<1, 256>>>();
    write_off<<<NB_SCAN, 256>>>();
    bucket_edges<<<eblk, 256>>>(ei, ew);

    // 2) layer 1: agg + gemm
    agg_csr_128<<<wblk, 256>>>(x0, a1h, a1l);
    gemm_mma<<<dim3(gblk, 2), 256>>>(a1h, a1l, INC, x0h, x0l, INC,
                                     wr1h, wr1l, INC, wo1h, wo1l, INC,
                                     b1, x1f, x1h, x1l, HID, 1);
    // 3) layer 2: agg + gemm (x2 only needed as bf16 splits)
    agg_csr_256<<<wblk, 256>>>(x1f, a2h, a2l);
    gemm_mma<<<dim3(gblk, 2), 256>>>(a2h, a2l, HID, x1h, x1l, HID,
                                     wr2h, wr2l, HID, wo2h, wo2l, HID,
                                     b2, (float*)0, x2h, x2l, HID, 1);
    // 4) head: out = x1 @ lin_w[:256] + x2 @ lin_w[256:]
    gemm_mma<<<dim3(gblk, 1), 256>>>(x1h, x1l, HID, x2h, x2l, HID,
                                     linh, linl, 2 * HID, linh + HID, linl + HID, 2 * HID,
                                     lin_b, out, (__nv_bfloat16*)0, (__nv_bfloat16*)0,
                                     OUTC, 0);
}

// round 7
// speedup vs baseline: 2.6577x; 1.1912x over previous
#include <cuda_runtime.h>
#include <cuda_bf16.h>
#include <stdint.h>

#define N_NODES 50000
#define E_EDGES 800000
#define INC 128
#define HID 256
#define OUTC 51
#define NB_SCAN 196   // ceil(50000/256)

// ---------------------------------------------------------------------------
// Scratch (static device globals -- allocation-free per harness rules)
// ---------------------------------------------------------------------------
__device__ __align__(16) __nv_bfloat16 g_x0h[N_NODES * INC], g_x0l[N_NODES * INC];
__device__ __align__(16) __nv_bfloat16 g_a1h[N_NODES * INC], g_a1l[N_NODES * INC];
__device__ __align__(16) float         g_x1f[N_NODES * HID];
__device__ __align__(16) __nv_bfloat16 g_x1h[N_NODES * HID], g_x1l[N_NODES * HID];
__device__ __align__(16) __nv_bfloat16 g_a2h[N_NODES * HID], g_a2l[N_NODES * HID];
__device__ __align__(16) __nv_bfloat16 g_x2h[N_NODES * HID], g_x2l[N_NODES * HID];
__device__ __align__(16) __nv_bfloat16 g_wr1h[HID * INC],  g_wr1l[HID * INC];
__device__ __align__(16) __nv_bfloat16 g_wo1h[HID * INC],  g_wo1l[HID * INC];
__device__ __align__(16) __nv_bfloat16 g_wr2h[HID * HID],  g_wr2l[HID * HID];
__device__ __align__(16) __nv_bfloat16 g_wo2h[HID * HID],  g_wo2l[HID * HID];
__device__ __align__(16) __nv_bfloat16 g_linh[OUTC * 2 * HID], g_linl[OUTC * 2 * HID];
// CSR
__device__ int   g_deg[N_NODES];
__device__ int   g_off[N_NODES + 1];
__device__ int   g_cur[N_NODES];
__device__ int   g_esrc[E_EDGES];
__device__ float g_eww[E_EDGES];
__device__ int   g_bsum[256];
__device__ int   g_bpre[256];
__device__ int   g_idx_is64;

// ---------------------------------------------------------------------------
// PTX helpers (baseline PTX only)
// ---------------------------------------------------------------------------
__device__ __forceinline__ uint32_t smem_u32(const void* p) {
    uint32_t a;
    asm("{ .reg .u64 t; cvta.to.shared.u64 t, %1; cvt.u32.u64 %0, t; }" : "=r"(a) : "l"(p));
    return a;
}
__device__ __forceinline__ void ldsm4(uint32_t addr, uint32_t& r0, uint32_t& r1,
                                      uint32_t& r2, uint32_t& r3) {
    asm volatile("ldmatrix.sync.aligned.m8n8.x4.shared.b16 {%0,%1,%2,%3}, [%4];"
                 : "=r"(r0), "=r"(r1), "=r"(r2), "=r"(r3) : "r"(addr));
}
__device__ __forceinline__ void mma16816(float* c, const uint32_t* a, const uint32_t* b) {
    asm volatile("mma.sync.aligned.m16n8k16.row.col.f32.bf16.bf16.f32 "
                 "{%0,%1,%2,%3}, {%4,%5,%6,%7}, {%8,%9}, {%0,%1,%2,%3};"
                 : "+f"(c[0]), "+f"(c[1]), "+f"(c[2]), "+f"(c[3])
                 : "r"(a[0]), "r"(a[1]), "r"(a[2]), "r"(a[3]), "r"(b[0]), "r"(b[1]));
}
// swizzled 16B-unit address inside a [rows x 32 bf16] tile (4 units/row)
__device__ __forceinline__ uint32_t tile_addr(uint32_t base, int r, int u) {
    int up = u ^ ((r >> 1) & 3);
    return base + (uint32_t)(r * 4 + up) * 16u;
}
__device__ __forceinline__ void cp16(uint32_t daddr, const void* src, int sz) {
    asm volatile("cp.async.cg.shared.global [%0], [%1], 16, %2;"
                 :: "r"(daddr), "l"(src), "r"(sz) : "memory");
}

// ---------------------------------------------------------------------------
// dtype detect (int64 per reference vs int32 from JAX x64-off)
// ---------------------------------------------------------------------------
__global__ void detect_idx(const void* __restrict__ ei) {
    int t = threadIdx.x;
    const long long* p = (const long long*)ei;
    int bad = 0;
    for (int i = t; i < 256; i += 32) {
        long long v = p[i];
        if (v < 0 || v >= N_NODES) bad = 1;
    }
    unsigned m = __ballot_sync(0xffffffffu, bad);
    if (t == 0) g_idx_is64 = (m == 0u);
}
__device__ __forceinline__ void load_edge(const void* ei, int e, int& src, int& dst) {
    if (g_idx_is64) {
        src = (int)((const long long*)ei)[e];
        dst = (int)((const long long*)ei)[E_EDGES + e];
    } else {
        src = ((const int*)ei)[e];
        dst = ((const int*)ei)[E_EDGES + e];
    }
}

// ---------------------------------------------------------------------------
// CSR build: histogram -> 3-kernel scan -> bucket
// ---------------------------------------------------------------------------
__global__ void zero_deg() {
    int i = blockIdx.x * blockDim.x + threadIdx.x;
    if (i < N_NODES) g_deg[i] = 0;
}
__global__ void hist_dst(const void* __restrict__ ei) {
    int e = blockIdx.x * blockDim.x + threadIdx.x;
    if (e >= E_EDGES) return;
    int src, dst;
    load_edge(ei, e, src, dst);
    atomicAdd(&g_deg[dst], 1);
}
__global__ void block_sum() {
    __shared__ int s[256];
    int b = blockIdx.x, t = threadIdx.x, i = b * 256 + t;
    s[t] = (i < N_NODES) ? g_deg[i] : 0;
    __syncthreads();
    for (int o = 128; o > 0; o >>= 1) { if (t < o) s[t] += s[t + o]; __syncthreads(); }
    if (t == 0) g_bsum[b] = s[0];
}
__global__ void scan_bsum() {
    __shared__ int s[256];
    int t = threadIdx.x;
    s[t] = (t < NB_SCAN) ? g_bsum[t] : 0;
    __syncthreads();
    for (int o = 1; o < 256; o <<= 1) {
        int v = (t >= o) ? s[t - o] : 0;
        __syncthreads();
        s[t] += v;
        __syncthreads();
    }
    g_bpre[t] = s[t];
}
__global__ void write_off() {
    __shared__ int s[256];
    int b = blockIdx.x, t = threadIdx.x, i = b * 256 + t;
    int v = (i < N_NODES) ? g_deg[i] : 0;
    s[t] = v;
    __syncthreads();
    for (int o = 1; o < 256; o <<= 1) {
        int u = (t >= o) ? s[t - o] : 0;
        __syncthreads();
        s[t] += u;
        __syncthreads();
    }
    int base = (b == 0) ? 0 : g_bpre[b - 1];
    int off = base + s[t] - v;
    if (i < N_NODES) {
        g_off[i] = off;
        g_cur[i] = off;
        if (i == N_NODES - 1) g_off[N_NODES] = off + v;
    }
}
__global__ void bucket_edges(const void* __restrict__ ei, const float* __restrict__ ew) {
    int e = blockIdx.x * blockDim.x + threadIdx.x;
    if (e >= E_EDGES) return;
    int src, dst;
    load_edge(ei, e, src, dst);
    int pos = atomicAdd(&g_cur[dst], 1);
    g_esrc[pos] = src;
    g_eww[pos]  = ew[e];
}

// ---------------------------------------------------------------------------
// bf16 hi/lo split helpers
// ---------------------------------------------------------------------------
__device__ __forceinline__ void split1(float v, __nv_bfloat16& h, __nv_bfloat16& l) {
    h = __float2bfloat16(v);
    l = __float2bfloat16(v - __bfloat162float(h));
}
__device__ __forceinline__ void store_split4(float4 a, __nv_bfloat16* ph, __nv_bfloat16* pl) {
    __nv_bfloat16 h0, h1, h2, h3, l0, l1, l2, l3;
    split1(a.x, h0, l0); split1(a.y, h1, l1); split1(a.z, h2, l2); split1(a.w, h3, l3);
    ((__nv_bfloat162*)ph)[0] = __halves2bfloat162(h0, h1);
    ((__nv_bfloat162*)ph)[1] = __halves2bfloat162(h2, h3);
    ((__nv_bfloat162*)pl)[0] = __halves2bfloat162(l0, l1);
    ((__nv_bfloat162*)pl)[1] = __halves2bfloat162(l2, l3);
}

// ---------------------------------------------------------------------------
// Fused prep: x0 split + all 5 weight transpose-splits in ONE kernel.
// ---------------------------------------------------------------------------
#define PX0   (N_NODES * INC)                 // 6,400,000
#define PW1   (INC * HID)                     // 32,768
#define PW2   (HID * HID)                     // 65,536
#define PLIN  (2 * HID * OUTC)                // 26,112
#define PREP_TOTAL (PX0 + 2 * PW1 + 2 * PW2 + PLIN)

__global__ void prep_all(const float* __restrict__ x0,
                         const float* __restrict__ wr1, const float* __restrict__ wo1,
                         const float* __restrict__ wr2, const float* __restrict__ wo2,
                         const float* __restrict__ lin) {
    long long i = (long long)blockIdx.x * blockDim.x + threadIdx.x;
    if (i >= PREP_TOTAL) return;
    __nv_bfloat16 hh, ll;
    if (i < PX0) {
        split1(x0[i], hh, ll);
        g_x0h[i] = hh; g_x0l[i] = ll;
        return;
    }
    long long j = i - PX0;
    const float* W; __nv_bfloat16 *th, *tl; int K, M; long long o;
    if (j < PW1)                { W = wr1; th = g_wr1h; tl = g_wr1l; K = INC; M = HID; o = j; }
    else if (j < 2 * PW1)       { W = wo1; th = g_wo1h; tl = g_wo1l; K = INC; M = HID; o = j - PW1; }
    else if (j < 2 * PW1 + PW2) { W = wr2; th = g_wr2h; tl = g_wr2l; K = HID; M = HID; o = j - 2 * PW1; }
    else if (j < 2 * PW1 + 2 * PW2) { W = wo2; th = g_wo2h; tl = g_wo2l; K = HID; M = HID; o = j - 2 * PW1 - PW2; }
    else                        { W = lin; th = g_linh; tl = g_linl; K = 2 * HID; M = OUTC; o = j - 2 * PW1 - 2 * PW2; }
    int k = (int)(o / M), m = (int)(o % M);
    split1(W[o], hh, ll);
    th[(size_t)m * K + k] = hh;
    tl[(size_t)m * K + k] = ll;
}

// ---------------------------------------------------------------------------
// CSR aggregation (warp per dst, fp32 register accumulate, bf16-split output)
// ---------------------------------------------------------------------------
__global__ __launch_bounds__(256)
void agg_csr_128(const float* __restrict__ x,
                 __nv_bfloat16* __restrict__ oh, __nv_bfloat16* __restrict__ ol) {
    int d = blockIdx.x * 8 + (threadIdx.x >> 5);
    if (d >= N_NODES) return;
    int lane = threadIdx.x & 31;
    int beg = g_off[d], end = g_off[d + 1];
    float4 acc = make_float4(0.f, 0.f, 0.f, 0.f);
    for (int k = beg; k < end; ++k) {
        int s = g_esrc[k]; float w = g_eww[k];
        float4 v = ((const float4*)(x + (size_t)s * INC))[lane];
        acc.x = fmaf(w, v.x, acc.x); acc.y = fmaf(w, v.y, acc.y);
        acc.z = fmaf(w, v.z, acc.z); acc.w = fmaf(w, v.w, acc.w);
    }
    store_split4(acc, oh + (size_t)d * INC + lane * 4, ol + (size_t)d * INC + lane * 4);
}

__global__ __launch_bounds__(256)
void agg_csr_256(const float* __restrict__ x,
                 __nv_bfloat16* __restrict__ oh, __nv_bfloat16* __restrict__ ol) {
    int d = blockIdx.x * 8 + (threadIdx.x >> 5);
    if (d >= N_NODES) return;
    int lane = threadIdx.x & 31;
    int beg = g_off[d], end = g_off[d + 1];
    float4 a0 = make_float4(0.f, 0.f, 0.f, 0.f);
    float4 a1 = make_float4(0.f, 0.f, 0.f, 0.f);
    for (int k = beg; k < end; ++k) {
        int s = g_esrc[k]; float w = g_eww[k];
        const float4* xr = (const float4*)(x + (size_t)s * HID);
        float4 v0 = xr[lane];
        float4 v1 = xr[lane + 32];
        a0.x = fmaf(w, v0.x, a0.x); a0.y = fmaf(w, v0.y, a0.y);
        a0.z = fmaf(w, v0.z, a0.z); a0.w = fmaf(w, v0.w, a0.w);
        a1.x = fmaf(w, v1.x, a1.x); a1.y = fmaf(w, v1.y, a1.y);
        a1.z = fmaf(w, v1.z, a1.z); a1.w = fmaf(w, v1.w, a1.w);
    }
    store_split4(a0, oh + (size_t)d * HID + lane * 4,       ol + (size_t)d * HID + lane * 4);
    store_split4(a1, oh + (size_t)d * HID + 128 + lane * 4, ol + (size_t)d * HID + 128 + lane * 4);
}

// ---------------------------------------------------------------------------
// Pipelined bf16 split-precision dual-source GEMM (cp.async double-buffered)
//   8 warps 4m x 2n; warp tile 32 x (BN/2); mma m16n8k16; 3 split terms.
// ---------------------------------------------------------------------------
template <int BN>
__global__ __launch_bounds__(256)
void gemm_mma(const __nv_bfloat16* __restrict__ A1h, const __nv_bfloat16* __restrict__ A1l, int K1,
              const __nv_bfloat16* __restrict__ A2h, const __nv_bfloat16* __restrict__ A2l, int K2,
              const __nv_bfloat16* __restrict__ B1h, const __nv_bfloat16* __restrict__ B1l, int pb1,
              const __nv_bfloat16* __restrict__ B2h, const __nv_bfloat16* __restrict__ B2l, int pb2,
              const float* __restrict__ bias,
              float* __restrict__ outF, __nv_bfloat16* __restrict__ outH,
              __nv_bfloat16* __restrict__ outL, int Mout, int doRelu) {
    constexpr int NG = BN / 16;          // n-groups per warp
    constexpr int NQ = BN / 32;          // B ldsm x4 per k-step
    constexpr int A_ELE = 128 * 32;      // bf16 elems per A tile
    constexpr int B_ELE = BN * 32;
    constexpr int STG = 2 * A_ELE + 2 * B_ELE;   // elems per stage

    extern __shared__ __align__(16) __nv_bfloat16 sm[];
    uint32_t base0 = smem_u32(sm);

    int tid = threadIdx.x, wid = tid >> 5, lane = tid & 31;
    int wm = (wid & 3) * 32;
    int wn = (wid >> 2) * (BN / 2);
    int row0 = blockIdx.x * 128;
    int col0 = blockIdx.y * BN;
    int rowsA = N_NODES - row0; if (rowsA > 128) rowsA = 128;
    int rowsB = Mout - col0;    if (rowsB > BN) rowsB = BN;

    const int nc1 = K1 / 32;
    const int NC = nc1 + K2 / 32;

    // stage chunk c into stage buffer st (cp.async, swizzled layout)
    auto stage_chunk = [&](int c, int st) {
        const __nv_bfloat16 *Ah, *Al, *Bh, *Bl;
        int pa, pb, kcol;
        if (c < nc1) { Ah = A1h; Al = A1l; pa = K1; Bh = B1h; Bl = B1l; pb = pb1; kcol = c * 32; }
        else         { Ah = A2h; Al = A2l; pa = K2; Bh = B2h; Bl = B2l; pb = pb2; kcol = (c - nc1) * 32; }
        Ah += (size_t)row0 * pa; Al += (size_t)row0 * pa;
        Bh += (size_t)col0 * pb; Bl += (size_t)col0 * pb;
        uint32_t sb = base0 + (uint32_t)st * STG * 2;
        // A tiles: 512 units each (h, l)
        for (int U = tid; U < 512; U += 256) {
            int r = U >> 2, u = U & 3;
            int up = u ^ ((r >> 1) & 3);
            int rs = (r < rowsA) ? r : 0;
            int sz = (r < rowsA) ? 16 : 0;
            uint32_t da = sb + (uint32_t)(r * 4 + up) * 16u;
            cp16(da,             Ah + (size_t)rs * pa + kcol + u * 8, sz);
            cp16(da + A_ELE * 2, Al + (size_t)rs * pa + kcol + u * 8, sz);
        }
        // B tiles: BN*4 units each (h, l)
        uint32_t bb = sb + 2u * (2 * A_ELE);
        for (int U = tid; U < BN * 4; U += 256) {
            int r = U >> 2, u = U & 3;
            int up = u ^ ((r >> 1) & 3);
            int rs = (r < rowsB) ? r : 0;
            int sz = (r < rowsB) ? 16 : 0;
            uint32_t da = bb + (uint32_t)(r * 4 + up) * 16u;
            cp16(da,             Bh + (size_t)rs * pb + kcol + u * 8, sz);
            cp16(da + B_ELE * 2, Bl + (size_t)rs * pb + kcol + u * 8, sz);
        }
    };

    float acc[2][NG][4];
#pragma unroll
    for (int i = 0; i < 2; ++i)
#pragma unroll
        for (int j = 0; j < NG; ++j)
#pragma unroll
            for (int q = 0; q < 4; ++q) acc[i][j][q] = 0.f;

    stage_chunk(0, 0);
    asm volatile("cp.async.commit_group;" ::: "memory");

    for (int c = 0; c < NC; ++c) {
        if (c + 1 < NC) {
            stage_chunk(c + 1, (c + 1) & 1);
            asm volatile("cp.async.commit_group;" ::: "memory");
            asm volatile("cp.async.wait_group 1;" ::: "memory");
        } else {
            asm volatile("cp.async.wait_group 0;" ::: "memory");
        }
        __syncthreads();

        uint32_t sb = base0 + (uint32_t)(c & 1) * STG * 2;
        uint32_t bAh = sb, bAl = sb + A_ELE * 2;
        uint32_t bBh = sb + 2u * (2 * A_ELE), bBl = bBh + B_ELE * 2;

#pragma unroll
        for (int ks = 0; ks < 2; ++ks) {
            int ksu = ks * 2;
            uint32_t fah[2][4], fal[2][4];
#pragma unroll
            for (int mt = 0; mt < 2; ++mt) {
                int r = wm + mt * 16 + (lane & 15);
                int u = ksu + (lane >> 4);
                ldsm4(tile_addr(bAh, r, u), fah[mt][0], fah[mt][1], fah[mt][2], fah[mt][3]);
                ldsm4(tile_addr(bAl, r, u), fal[mt][0], fal[mt][1], fal[mt][2], fal[mt][3]);
            }
            uint32_t fbh[NQ][4], fbl[NQ][4];
#pragma unroll
            for (int q = 0; q < NQ; ++q) {
                int r = wn + q * 16 + (lane & 7) + ((lane & 16) ? 8 : 0);
                int u = ksu + ((lane >> 3) & 1);
                ldsm4(tile_addr(bBh, r, u), fbh[q][0], fbh[q][1], fbh[q][2], fbh[q][3]);
                ldsm4(tile_addr(bBl, r, u), fbl[q][0], fbl[q][1], fbl[q][2], fbl[q][3]);
            }
#pragma unroll
            for (int mt = 0; mt < 2; ++mt)
#pragma unroll
                for (int ng = 0; ng < NG; ++ng) {
                    const uint32_t* bpH = &fbh[ng >> 1][(ng & 1) * 2];
                    const uint32_t* bpL = &fbl[ng >> 1][(ng & 1) * 2];
                    mma16816(acc[mt][ng], fah[mt], bpH);
                    mma16816(acc[mt][ng], fah[mt], bpL);
                    mma16816(acc[mt][ng], fal[mt], bpH);
                }
        }
        __syncthreads();
    }

    // Epilogue
#pragma unroll
    for (int mt = 0; mt < 2; ++mt) {
        int rg = row0 + wm + mt * 16 + (lane >> 2);
#pragma unroll
        for (int half = 0; half < 2; ++half) {
            int r = rg + half * 8;
            if (r >= N_NODES) continue;
#pragma unroll
            for (int ng = 0; ng < NG; ++ng) {
                int c0 = col0 + wn + ng * 8 + (lane & 3) * 2;
#pragma unroll
                for (int q = 0; q < 2; ++q) {
                    int c = c0 + q;
                    if (c >= Mout) continue;
                    float v = acc[mt][ng][half * 2 + q] + bias[c];
                    if (doRelu) v = fmaxf(v, 0.f);
                    size_t idx = (size_t)r * Mout + c;
                    if (outF) outF[idx] = v;
                    if (outH) {
                        __nv_bfloat16 hh, ll;
                        split1(v, hh, ll);
                        outH[idx] = hh;
                        outL[idx] = ll;
                    }
                }
            }
        }
    }
}

// ---------------------------------------------------------------------------
extern "C" void kernel_launch(void* const* d_in, const int* in_sizes, int n_in,
                              void* d_out, int out_size) {
    const float* x0      = (const float*)d_in[0];
    const void*  ei      = d_in[1];
    const float* ew      = (const float*)d_in[2];
    const float* w_rel1  = (const float*)d_in[3];
    const float* b1      = (const float*)d_in[4];
    const float* w_root1 = (const float*)d_in[5];
    const float* w_rel2  = (const float*)d_in[6];
    const float* b2      = (const float*)d_in[7];
    const float* w_root2 = (const float*)d_in[8];
    const float* lin_w   = (const float*)d_in[9];
    const float* lin_b   = (const float*)d_in[10];
    float*       out     = (float*)d_out;

#define SYM(p, s) cudaGetSymbolAddress((void**)&p, s)
    __nv_bfloat16 *x0h, *x0l, *a1h, *a1l, *x1h, *x1l, *a2h, *a2l, *x2h, *x2l;
    __nv_bfloat16 *wr1h, *wr1l, *wo1h, *wo1l, *wr2h, *wr2l, *wo2h, *wo2l, *linh, *linl;
    float *x1f;
    SYM(x0h, g_x0h); SYM(x0l, g_x0l); SYM(a1h, g_a1h); SYM(a1l, g_a1l);
    SYM(x1f, g_x1f); SYM(x1h, g_x1h); SYM(x1l, g_x1l);
    SYM(a2h, g_a2h); SYM(a2l, g_a2l); SYM(x2h, g_x2h); SYM(x2l, g_x2l);
    SYM(wr1h, g_wr1h); SYM(wr1l, g_wr1l); SYM(wo1h, g_wo1h); SYM(wo1l, g_wo1l);
    SYM(wr2h, g_wr2h); SYM(wr2l, g_wr2l); SYM(wo2h, g_wo2h); SYM(wo2l, g_wo2l);
    SYM(linh, g_linh); SYM(linl, g_linl);
#undef SYM

    // dynamic smem: 2 stages x (2 A tiles + 2 B tiles)
    const int SM128 = 2 * (2 * 128 * 32 + 2 * 128 * 32) * 2;  // 65536 B
    const int SM64  = 2 * (2 * 128 * 32 + 2 * 64 * 32) * 2;   // 49152 B
    cudaFuncSetAttribute(gemm_mma<128>, cudaFuncAttributeMaxDynamicSharedMemorySize, SM128);
    cudaFuncSetAttribute(gemm_mma<64>,  cudaFuncAttributeMaxDynamicSharedMemorySize, SM64);

    const int eblk = (E_EDGES + 255) / 256;
    const int wblk = (N_NODES + 7) / 8;
    const int gblk = (N_NODES + 127) / 128;   // 391

    // 0) dtype detect + fused prep (x0 split + all weight transposes)
    detect_idx<<<1, 32>>>(ei);
    prep_all<<<(PREP_TOTAL + 255) / 256, 256>>>(x0, w_rel1, w_root1, w_rel2, w_root2, lin_w);

    // 1) CSR build
    zero_deg<<<NB_SCAN, 256>>>();
    hist_dst<<<eblk, 256>>>(ei);
    block_sum<<<NB_SCAN, 256>>>();
    scan_bsum<<<1, 256>>>();
    write_off<<<NB_SCAN, 256>>>();
    bucket_edges<<<eblk, 256>>>(ei, ew);

    // 2) layer 1: agg + gemm
    agg_csr_128<<<wblk, 256>>>(x0, a1h, a1l);
    gemm_mma<128><<<dim3(gblk, 2), 256, SM128>>>(a1h, a1l, INC, x0h, x0l, INC,
                                                 wr1h, wr1l, INC, wo1h, wo1l, INC,
                                                 b1, x1f, x1h, x1l, HID, 1);
    // 3) layer 2: agg + gemm
    agg_csr_256<<<wblk, 256>>>(x1f, a2h, a2l);
    gemm_mma<128><<<dim3(gblk, 2), 256, SM128>>>(a2h, a2l, HID, x1h, x1l, HID,
                                                 wr2h, wr2l, HID, wo2h, wo2l, HID,
                                                 b2, (float*)0, x2h, x2l, HID, 1);
    // 4) head: out = x1 @ lin_w[:256] + x2 @ lin_w[256:]  (BN=64 tile)
    gemm_mma<64><<<dim3(gblk, 1), 256, SM64>>>(x1h, x1l, HID, x2h, x2l, HID,
                                               linh, linl, 2 * HID, linh + HID, linl + HID, 2 * HID,
                                               lin_b, out, (__nv_bfloat16*)0, (__nv_bfloat16*)0,
                                               OUTC, 0);
}

// round 8
// speedup vs baseline: 2.7351x; 1.0291x over previous
#include <cuda_runtime.h>
#include <cuda_bf16.h>
#include <cuda_fp16.h>
#include <stdint.h>

#define N_NODES 50000
#define E_EDGES 800000
#define INC 128
#define HID 256
#define OUTC 51
#define NB_SCAN 196   // ceil(50000/256)

// ---------------------------------------------------------------------------
// Scratch (static device globals -- allocation-free per harness rules)
// ---------------------------------------------------------------------------
__device__ __align__(16) __nv_bfloat16 g_x0h[N_NODES * INC], g_x0l[N_NODES * INC];
__device__ __align__(16) __nv_bfloat16 g_a1h[N_NODES * INC], g_a1l[N_NODES * INC];
__device__ __align__(16) __half        g_x1p[N_NODES * HID];          // fp16 x1 (messages)
__device__ __align__(16) __nv_bfloat16 g_x1h[N_NODES * HID], g_x1l[N_NODES * HID];
__device__ __align__(16) __nv_bfloat16 g_a2h[N_NODES * HID], g_a2l[N_NODES * HID];
__device__ __align__(16) __nv_bfloat16 g_x2h[N_NODES * HID], g_x2l[N_NODES * HID];
__device__ __align__(16) __nv_bfloat16 g_wr1h[HID * INC],  g_wr1l[HID * INC];
__device__ __align__(16) __nv_bfloat16 g_wo1h[HID * INC],  g_wo1l[HID * INC];
__device__ __align__(16) __nv_bfloat16 g_wr2h[HID * HID],  g_wr2l[HID * HID];
__device__ __align__(16) __nv_bfloat16 g_wo2h[HID * HID],  g_wo2l[HID * HID];
__device__ __align__(16) __nv_bfloat16 g_linh[OUTC * 2 * HID], g_linl[OUTC * 2 * HID];
// CSR
__device__ int   g_deg[N_NODES];
__device__ int   g_off[N_NODES];
__device__ int   g_cur[N_NODES];      // after bucket_edges: end of each bucket
__device__ int   g_esrc[E_EDGES];
__device__ float g_eww[E_EDGES];
__device__ int   g_total;
__device__ int   g_idx_is64;

// ---------------------------------------------------------------------------
// PTX helpers (baseline PTX only)
// ---------------------------------------------------------------------------
__device__ __forceinline__ uint32_t smem_u32(const void* p) {
    uint32_t a;
    asm("{ .reg .u64 t; cvta.to.shared.u64 t, %1; cvt.u32.u64 %0, t; }" : "=r"(a) : "l"(p));
    return a;
}
__device__ __forceinline__ void ldsm4(uint32_t addr, uint32_t& r0, uint32_t& r1,
                                      uint32_t& r2, uint32_t& r3) {
    asm volatile("ldmatrix.sync.aligned.m8n8.x4.shared.b16 {%0,%1,%2,%3}, [%4];"
                 : "=r"(r0), "=r"(r1), "=r"(r2), "=r"(r3) : "r"(addr));
}
__device__ __forceinline__ void mma16816(float* c, const uint32_t* a, const uint32_t* b) {
    asm volatile("mma.sync.aligned.m16n8k16.row.col.f32.bf16.bf16.f32 "
                 "{%0,%1,%2,%3}, {%4,%5,%6,%7}, {%8,%9}, {%0,%1,%2,%3};"
                 : "+f"(c[0]), "+f"(c[1]), "+f"(c[2]), "+f"(c[3])
                 : "r"(a[0]), "r"(a[1]), "r"(a[2]), "r"(a[3]), "r"(b[0]), "r"(b[1]));
}
__device__ __forceinline__ uint32_t tile_addr(uint32_t base, int r, int u) {
    int up = u ^ ((r >> 1) & 3);
    return base + (uint32_t)(r * 4 + up) * 16u;
}
__device__ __forceinline__ void cp16(uint32_t daddr, const void* src, int sz) {
    asm volatile("cp.async.cg.shared.global [%0], [%1], 16, %2;"
                 :: "r"(daddr), "l"(src), "r"(sz) : "memory");
}

// ---------------------------------------------------------------------------
// dtype detect + zero scan base
// ---------------------------------------------------------------------------
__global__ void detect_idx(const void* __restrict__ ei) {
    int t = threadIdx.x;
    const long long* p = (const long long*)ei;
    int bad = 0;
    for (int i = t; i < 256; i += 32) {
        long long v = p[i];
        if (v < 0 || v >= N_NODES) bad = 1;
    }
    unsigned m = __ballot_sync(0xffffffffu, bad);
    if (t == 0) { g_idx_is64 = (m == 0u); g_total = 0; }
}
__device__ __forceinline__ void load_edge(const void* ei, int e, int& src, int& dst) {
    if (g_idx_is64) {
        src = (int)((const long long*)ei)[e];
        dst = (int)((const long long*)ei)[E_EDGES + e];
    } else {
        src = ((const int*)ei)[e];
        dst = ((const int*)ei)[E_EDGES + e];
    }
}

// ---------------------------------------------------------------------------
// CSR build: hist -> one-pass scan (atomic base) -> bucket
// Bucket layout need not be monotone in d; agg reads [g_off[d], g_cur[d]).
// ---------------------------------------------------------------------------
__global__ void hist_dst(const void* __restrict__ ei) {
    int e = blockIdx.x * blockDim.x + threadIdx.x;
    if (e >= E_EDGES) return;
    int src, dst;
    load_edge(ei, e, src, dst);
    atomicAdd(&g_deg[dst], 1);
}
__global__ void scan_one() {
    __shared__ int s[256];
    __shared__ int sh_base;
    int b = blockIdx.x, t = threadIdx.x, i = b * 256 + t;
    int v = (i < N_NODES) ? g_deg[i] : 0;
    s[t] = v;
    __syncthreads();
    for (int o = 1; o < 256; o <<= 1) {
        int u = (t >= o) ? s[t - o] : 0;
        __syncthreads();
        s[t] += u;
        __syncthreads();
    }
    if (t == 255) sh_base = atomicAdd(&g_total, s[255]);
    __syncthreads();
    if (i < N_NODES) {
        int off = sh_base + s[t] - v;
        g_off[i] = off;
        g_cur[i] = off;
    }
}
__global__ void bucket_edges(const void* __restrict__ ei, const float* __restrict__ ew) {
    int e = blockIdx.x * blockDim.x + threadIdx.x;
    if (e >= E_EDGES) return;
    int src, dst;
    load_edge(ei, e, src, dst);
    int pos = atomicAdd(&g_cur[dst], 1);
    g_esrc[pos] = src;
    g_eww[pos]  = ew[e];
}

// ---------------------------------------------------------------------------
// bf16 hi/lo split helpers
// ---------------------------------------------------------------------------
__device__ __forceinline__ void split1(float v, __nv_bfloat16& h, __nv_bfloat16& l) {
    h = __float2bfloat16(v);
    l = __float2bfloat16(v - __bfloat162float(h));
}
__device__ __forceinline__ void store_split4(float4 a, __nv_bfloat16* ph, __nv_bfloat16* pl) {
    __nv_bfloat16 h0, h1, h2, h3, l0, l1, l2, l3;
    split1(a.x, h0, l0); split1(a.y, h1, l1); split1(a.z, h2, l2); split1(a.w, h3, l3);
    ((__nv_bfloat162*)ph)[0] = __halves2bfloat162(h0, h1);
    ((__nv_bfloat162*)ph)[1] = __halves2bfloat162(h2, h3);
    ((__nv_bfloat162*)pl)[0] = __halves2bfloat162(l0, l1);
    ((__nv_bfloat162*)pl)[1] = __halves2bfloat162(l2, l3);
}

// ---------------------------------------------------------------------------
// Fused prep: x0 split + 5 weight transpose-splits + deg zeroing, ONE kernel.
// ---------------------------------------------------------------------------
#define PX0   (N_NODES * INC)                 // 6,400,000
#define PW1   (INC * HID)                     // 32,768
#define PW2   (HID * HID)                     // 65,536
#define PLIN  (2 * HID * OUTC)                // 26,112
#define PWSUM (2 * PW1 + 2 * PW2 + PLIN)
#define PREP_TOTAL (PX0 + PWSUM + N_NODES)

__global__ void prep_all(const float* __restrict__ x0,
                         const float* __restrict__ wr1, const float* __restrict__ wo1,
                         const float* __restrict__ wr2, const float* __restrict__ wo2,
                         const float* __restrict__ lin) {
    long long i = (long long)blockIdx.x * blockDim.x + threadIdx.x;
    if (i >= PREP_TOTAL) return;
    __nv_bfloat16 hh, ll;
    if (i < PX0) {
        split1(x0[i], hh, ll);
        g_x0h[i] = hh; g_x0l[i] = ll;
        return;
    }
    long long j = i - PX0;
    if (j >= PWSUM) {                 // deg zero range
        g_deg[j - PWSUM] = 0;
        return;
    }
    const float* W; __nv_bfloat16 *th, *tl; int K, M; long long o;
    if (j < PW1)                { W = wr1; th = g_wr1h; tl = g_wr1l; K = INC; M = HID; o = j; }
    else if (j < 2 * PW1)       { W = wo1; th = g_wo1h; tl = g_wo1l; K = INC; M = HID; o = j - PW1; }
    else if (j < 2 * PW1 + PW2) { W = wr2; th = g_wr2h; tl = g_wr2l; K = HID; M = HID; o = j - 2 * PW1; }
    else if (j < 2 * PW1 + 2 * PW2) { W = wo2; th = g_wo2h; tl = g_wo2l; K = HID; M = HID; o = j - 2 * PW1 - PW2; }
    else                        { W = lin; th = g_linh; tl = g_linl; K = 2 * HID; M = OUTC; o = j - 2 * PW1 - 2 * PW2; }
    int k = (int)(o / M), m = (int)(o % M);
    split1(W[o], hh, ll);
    th[(size_t)m * K + k] = hh;
    tl[(size_t)m * K + k] = ll;
}

// ---------------------------------------------------------------------------
// CSR aggregation (warp per dst, fp32 accumulate, bf16-split output)
// ---------------------------------------------------------------------------
__global__ __launch_bounds__(256)
void agg_csr_128(const float* __restrict__ x,
                 __nv_bfloat16* __restrict__ oh, __nv_bfloat16* __restrict__ ol) {
    int d = blockIdx.x * 8 + (threadIdx.x >> 5);
    if (d >= N_NODES) return;
    int lane = threadIdx.x & 31;
    int beg = g_off[d], end = g_cur[d];
    float4 acc = make_float4(0.f, 0.f, 0.f, 0.f);
    for (int k = beg; k < end; ++k) {
        int s = g_esrc[k]; float w = g_eww[k];
        float4 v = ((const float4*)(x + (size_t)s * INC))[lane];
        acc.x = fmaf(w, v.x, acc.x); acc.y = fmaf(w, v.y, acc.y);
        acc.z = fmaf(w, v.z, acc.z); acc.w = fmaf(w, v.w, acc.w);
    }
    store_split4(acc, oh + (size_t)d * INC + lane * 4, ol + (size_t)d * INC + lane * 4);
}

// layer 2: gather fp16 x1 rows (one uint4 = 8 halves per lane)
__global__ __launch_bounds__(256)
void agg_csr_256h(const __half* __restrict__ x,
                  __nv_bfloat16* __restrict__ oh, __nv_bfloat16* __restrict__ ol) {
    int d = blockIdx.x * 8 + (threadIdx.x >> 5);
    if (d >= N_NODES) return;
    int lane = threadIdx.x & 31;
    int beg = g_off[d], end = g_cur[d];
    float acc[8];
#pragma unroll
    for (int j = 0; j < 8; ++j) acc[j] = 0.f;
    for (int k = beg; k < end; ++k) {
        int s = g_esrc[k]; float w = g_eww[k];
        uint4 p = ((const uint4*)(x + (size_t)s * HID))[lane];
        const __half2* hp = (const __half2*)&p;
#pragma unroll
        for (int j = 0; j < 4; ++j) {
            float2 f = __half22float2(hp[j]);
            acc[2 * j]     = fmaf(w, f.x, acc[2 * j]);
            acc[2 * j + 1] = fmaf(w, f.y, acc[2 * j + 1]);
        }
    }
    float4 a0 = make_float4(acc[0], acc[1], acc[2], acc[3]);
    float4 a1 = make_float4(acc[4], acc[5], acc[6], acc[7]);
    size_t o = (size_t)d * HID + lane * 8;
    store_split4(a0, oh + o,     ol + o);
    store_split4(a1, oh + o + 4, ol + o + 4);
}

// ---------------------------------------------------------------------------
// Pipelined bf16 split-precision dual-source GEMM (cp.async double-buffered)
// ---------------------------------------------------------------------------
template <int BN>
__global__ __launch_bounds__(256)
void gemm_mma(const __nv_bfloat16* __restrict__ A1h, const __nv_bfloat16* __restrict__ A1l, int K1,
              const __nv_bfloat16* __restrict__ A2h, const __nv_bfloat16* __restrict__ A2l, int K2,
              const __nv_bfloat16* __restrict__ B1h, const __nv_bfloat16* __restrict__ B1l, int pb1,
              const __nv_bfloat16* __restrict__ B2h, const __nv_bfloat16* __restrict__ B2l, int pb2,
              const float* __restrict__ bias,
              float* __restrict__ outF, __half* __restrict__ outP,
              __nv_bfloat16* __restrict__ outH, __nv_bfloat16* __restrict__ outL,
              int Mout, int doRelu) {
    constexpr int NG = BN / 16;
    constexpr int NQ = BN / 32;
    constexpr int A_ELE = 128 * 32;
    constexpr int B_ELE = BN * 32;
    constexpr int STG = 2 * A_ELE + 2 * B_ELE;

    extern __shared__ __align__(16) __nv_bfloat16 sm[];
    uint32_t base0 = smem_u32(sm);

    int tid = threadIdx.x, wid = tid >> 5, lane = tid & 31;
    int wm = (wid & 3) * 32;
    int wn = (wid >> 2) * (BN / 2);
    int row0 = blockIdx.x * 128;
    int col0 = blockIdx.y * BN;
    int rowsA = N_NODES - row0; if (rowsA > 128) rowsA = 128;
    int rowsB = Mout - col0;    if (rowsB > BN) rowsB = BN;

    const int nc1 = K1 / 32;
    const int NC = nc1 + K2 / 32;

    auto stage_chunk = [&](int c, int st) {
        const __nv_bfloat16 *Ah, *Al, *Bh, *Bl;
        int pa, pb, kcol;
        if (c < nc1) { Ah = A1h; Al = A1l; pa = K1; Bh = B1h; Bl = B1l; pb = pb1; kcol = c * 32; }
        else         { Ah = A2h; Al = A2l; pa = K2; Bh = B2h; Bl = B2l; pb = pb2; kcol = (c - nc1) * 32; }
        Ah += (size_t)row0 * pa; Al += (size_t)row0 * pa;
        Bh += (size_t)col0 * pb; Bl += (size_t)col0 * pb;
        uint32_t sb = base0 + (uint32_t)st * STG * 2;
        for (int U = tid; U < 512; U += 256) {
            int r = U >> 2, u = U & 3;
            int up = u ^ ((r >> 1) & 3);
            int rs = (r < rowsA) ? r : 0;
            int sz = (r < rowsA) ? 16 : 0;
            uint32_t da = sb + (uint32_t)(r * 4 + up) * 16u;
            cp16(da,             Ah + (size_t)rs * pa + kcol + u * 8, sz);
            cp16(da + A_ELE * 2, Al + (size_t)rs * pa + kcol + u * 8, sz);
        }
        uint32_t bb = sb + 2u * (2 * A_ELE);
        for (int U = tid; U < BN * 4; U += 256) {
            int r = U >> 2, u = U & 3;
            int up = u ^ ((r >> 1) & 3);
            int rs = (r < rowsB) ? r : 0;
            int sz = (r < rowsB) ? 16 : 0;
            uint32_t da = bb + (uint32_t)(r * 4 + up) * 16u;
            cp16(da,             Bh + (size_t)rs * pb + kcol + u * 8, sz);
            cp16(da + B_ELE * 2, Bl + (size_t)rs * pb + kcol + u * 8, sz);
        }
    };

    float acc[2][NG][4];
#pragma unroll
    for (int i = 0; i < 2; ++i)
#pragma unroll
        for (int j = 0; j < NG; ++j)
#pragma unroll
            for (int q = 0; q < 4; ++q) acc[i][j][q] = 0.f;

    stage_chunk(0, 0);
    asm volatile("cp.async.commit_group;" ::: "memory");

    for (int c = 0; c < NC; ++c) {
        if (c + 1 < NC) {
            stage_chunk(c + 1, (c + 1) & 1);
            asm volatile("cp.async.commit_group;" ::: "memory");
            asm volatile("cp.async.wait_group 1;" ::: "memory");
        } else {
            asm volatile("cp.async.wait_group 0;" ::: "memory");
        }
        __syncthreads();

        uint32_t sb = base0 + (uint32_t)(c & 1) * STG * 2;
        uint32_t bAh = sb, bAl = sb + A_ELE * 2;
        uint32_t bBh = sb + 2u * (2 * A_ELE), bBl = bBh + B_ELE * 2;

#pragma unroll
        for (int ks = 0; ks < 2; ++ks) {
            int ksu = ks * 2;
            uint32_t fah[2][4], fal[2][4];
#pragma unroll
            for (int mt = 0; mt < 2; ++mt) {
                int r = wm + mt * 16 + (lane & 15);
                int u = ksu + (lane >> 4);
                ldsm4(tile_addr(bAh, r, u), fah[mt][0], fah[mt][1], fah[mt][2], fah[mt][3]);
                ldsm4(tile_addr(bAl, r, u), fal[mt][0], fal[mt][1], fal[mt][2], fal[mt][3]);
            }
            uint32_t fbh[NQ][4], fbl[NQ][4];
#pragma unroll
            for (int q = 0; q < NQ; ++q) {
                int r = wn + q * 16 + (lane & 7) + ((lane & 16) ? 8 : 0);
                int u = ksu + ((lane >> 3) & 1);
                ldsm4(tile_addr(bBh, r, u), fbh[q][0], fbh[q][1], fbh[q][2], fbh[q][3]);
                ldsm4(tile_addr(bBl, r, u), fbl[q][0], fbl[q][1], fbl[q][2], fbl[q][3]);
            }
#pragma unroll
            for (int mt = 0; mt < 2; ++mt)
#pragma unroll
                for (int ng = 0; ng < NG; ++ng) {
                    const uint32_t* bpH = &fbh[ng >> 1][(ng & 1) * 2];
                    const uint32_t* bpL = &fbl[ng >> 1][(ng & 1) * 2];
                    mma16816(acc[mt][ng], fah[mt], bpH);
                    mma16816(acc[mt][ng], fah[mt], bpL);
                    mma16816(acc[mt][ng], fal[mt], bpH);
                }
        }
        __syncthreads();
    }

    // Epilogue
#pragma unroll
    for (int mt = 0; mt < 2; ++mt) {
        int rg = row0 + wm + mt * 16 + (lane >> 2);
#pragma unroll
        for (int half = 0; half < 2; ++half) {
            int r = rg + half * 8;
            if (r >= N_NODES) continue;
#pragma unroll
            for (int ng = 0; ng < NG; ++ng) {
                int c0 = col0 + wn + ng * 8 + (lane & 3) * 2;
#pragma unroll
                for (int q = 0; q < 2; ++q) {
                    int c = c0 + q;
                    if (c >= Mout) continue;
                    float v = acc[mt][ng][half * 2 + q] + bias[c];
                    if (doRelu) v = fmaxf(v, 0.f);
                    size_t idx = (size_t)r * Mout + c;
                    if (outF) outF[idx] = v;
                    if (outP) outP[idx] = __float2half(v);
                    if (outH) {
                        __nv_bfloat16 hh, ll;
                        split1(v, hh, ll);
                        outH[idx] = hh;
                        outL[idx] = ll;
                    }
                }
            }
        }
    }
}

// ---------------------------------------------------------------------------
extern "C" void kernel_launch(void* const* d_in, const int* in_sizes, int n_in,
                              void* d_out, int out_size) {
    const float* x0      = (const float*)d_in[0];
    const void*  ei      = d_in[1];
    const float* ew      = (const float*)d_in[2];
    const float* w_rel1  = (const float*)d_in[3];
    const float* b1      = (const float*)d_in[4];
    const float* w_root1 = (const float*)d_in[5];
    const float* w_rel2  = (const float*)d_in[6];
    const float* b2      = (const float*)d_in[7];
    const float* w_root2 = (const float*)d_in[8];
    const float* lin_w   = (const float*)d_in[9];
    const float* lin_b   = (const float*)d_in[10];
    float*       out     = (float*)d_out;

#define SYM(p, s) cudaGetSymbolAddress((void**)&p, s)
    __nv_bfloat16 *x0h, *x0l, *a1h, *a1l, *x1h, *x1l, *a2h, *a2l, *x2h, *x2l;
    __nv_bfloat16 *wr1h, *wr1l, *wo1h, *wo1l, *wr2h, *wr2l, *wo2h, *wo2l, *linh, *linl;
    __half *x1p;
    SYM(x0h, g_x0h); SYM(x0l, g_x0l); SYM(a1h, g_a1h); SYM(a1l, g_a1l);
    SYM(x1p, g_x1p); SYM(x1h, g_x1h); SYM(x1l, g_x1l);
    SYM(a2h, g_a2h); SYM(a2l, g_a2l); SYM(x2h, g_x2h); SYM(x2l, g_x2l);
    SYM(wr1h, g_wr1h); SYM(wr1l, g_wr1l); SYM(wo1h, g_wo1h); SYM(wo1l, g_wo1l);
    SYM(wr2h, g_wr2h); SYM(wr2l, g_wr2l); SYM(wo2h, g_wo2h); SYM(wo2l, g_wo2l);
    SYM(linh, g_linh); SYM(linl, g_linl);
#undef SYM

    const int SM128 = 2 * (2 * 128 * 32 + 2 * 128 * 32) * 2;  // 65536 B
    const int SM64  = 2 * (2 * 128 * 32 + 2 * 64 * 32) * 2;   // 49152 B
    cudaFuncSetAttribute(gemm_mma<128>, cudaFuncAttributeMaxDynamicSharedMemorySize, SM128);
    cudaFuncSetAttribute(gemm_mma<64>,  cudaFuncAttributeMaxDynamicSharedMemorySize, SM64);

    const int eblk = (E_EDGES + 255) / 256;
    const int wblk = (N_NODES + 7) / 8;
    const int gblk = (N_NODES + 127) / 128;   // 391

    // 0) detect + fused prep (x0 split, weight transposes, deg zero)
    detect_idx<<<1, 32>>>(ei);
    prep_all<<<(PREP_TOTAL + 255) / 256, 256>>>(x0, w_rel1, w_root1, w_rel2, w_root2, lin_w);

    // 1) CSR build (hist -> one-pass scan -> bucket)
    hist_dst<<<eblk, 256>>>(ei);
    scan_one<<<NB_SCAN, 256>>>();
    bucket_edges<<<eblk, 256>>>(ei, ew);

    // 2) layer 1
    agg_csr_128<<<wblk, 256>>>(x0, a1h, a1l);
    gemm_mma<128><<<dim3(gblk, 2), 256, SM128>>>(a1h, a1l, INC, x0h, x0l, INC,
                                                 wr1h, wr1l, INC, wo1h, wo1l, INC,
                                                 b1, (float*)0, x1p, x1h, x1l, HID, 1);
    // 3) layer 2 (messages gathered in fp16)
    agg_csr_256h<<<wblk, 256>>>(x1p, a2h, a2l);
    gemm_mma<128><<<dim3(gblk, 2), 256, SM128>>>(a2h, a2l, HID, x1h, x1l, HID,
                                                 wr2h, wr2l, HID, wo2h, wo2l, HID,
                                                 b2, (float*)0, (__half*)0, x2h, x2l, HID, 1);
    // 4) head
    gemm_mma<64><<<dim3(gblk, 1), 256, SM64>>>(x1h, x1l, HID, x2h, x2l, HID,
                                               linh, linl, 2 * HID, linh + HID, linl + HID, 2 * HID,
                                               lin_b, out, (__half*)0,
                                               (__nv_bfloat16*)0, (__nv_bfloat16*)0,
                                               OUTC, 0);
}